// round 4
// baseline (speedup 1.0000x reference)
#include <cuda_runtime.h>
#include <cuda_bf16.h>

#define NB      8192
#define STEPS   50
#define HID     64

// Scratch for nearest-neighbor c0 values (no cudaMalloc allowed).
__device__ float g_c0[NB];

// ---------------------------------------------------------------------------
// Kernel 1: 1-D nearest neighbor, 8 lanes per sample (full-chip parallel).
// Compare on |ci - cj| (exactly the reference metric for CD=1: norm == abs).
// Self excluded by index. Lexicographic (dist, index) merge preserves the
// reference's argmin-first-index tie break.
// ---------------------------------------------------------------------------
__global__ void __launch_bounds__(256) nn_kernel(const float* __restrict__ c, int B)
{
    __shared__ float sc[NB];
    const int tid = threadIdx.x;
    const float4* c4 = (const float4*)c;
    float4* s4 = (float4*)sc;
    for (int j = tid; j < NB / 4; j += 256) s4[j] = c4[j];
    __syncthreads();

    const int gt = blockIdx.x * 256 + tid;
    const int s  = gt >> 3;          // sample id
    const int r  = gt & 7;           // chunk id (8 chunks of 1024)
    const float ci = sc[s];

    const int j0 = r * (NB / 8);
    float best = 3.0e38f;
    int   bj   = j0;

    #pragma unroll 4
    for (int j = j0; j < j0 + NB / 8; j += 4) {
        float4 v = *(const float4*)&sc[j];
        {
            float d = fabsf(ci - v.x);
            d = (j + 0 == s) ? 3.0e38f : d;
            if (d < best) { best = d; bj = j + 0; }
        }
        {
            float d = fabsf(ci - v.y);
            d = (j + 1 == s) ? 3.0e38f : d;
            if (d < best) { best = d; bj = j + 1; }
        }
        {
            float d = fabsf(ci - v.z);
            d = (j + 2 == s) ? 3.0e38f : d;
            if (d < best) { best = d; bj = j + 2; }
        }
        {
            float d = fabsf(ci - v.w);
            d = (j + 3 == s) ? 3.0e38f : d;
            if (d < best) { best = d; bj = j + 3; }
        }
    }

    #pragma unroll
    for (int off = 4; off; off >>= 1) {
        float ob = __shfl_xor_sync(0xffffffffu, best, off, 8);
        int   oj = __shfl_xor_sync(0xffffffffu, bj,   off, 8);
        if (ob < best || (ob == best && oj < bj)) { best = ob; bj = oj; }
    }
    if (r == 0) g_c0[s] = sc[bj];
}

// ---------------------------------------------------------------------------
// Kernel 2: warp-per-sample solve, piecewise-linear-in-y with affine caching.
//
// Steady state: z1 = a1 + y*w1y ; z2 = ub + y*t ; z3 = rb + y*s (6 FMA) and
// ONE ballot detects any of the 192 mask bits changing (gy is constant in y
// within a linear region). Slow path re-derives level by level.
//
// FIX vs previous round: level-2 recompute condition must include "level-1
// matvec re-ran" (did1) — if (ub,t) changed, (rb,s) are stale even when the
// m2 sign pattern is unchanged. did1/did2 are ballot results (warp-uniform).
// ---------------------------------------------------------------------------
__global__ void __launch_bounds__(256) solve_kernel(
    const float* __restrict__ x,
    const float* __restrict__ W1, const float* __restrict__ b1,
    const float* __restrict__ W2, const float* __restrict__ b2,
    const float* __restrict__ W3, const float* __restrict__ b3,
    const float* __restrict__ W4,
    float* __restrict__ out, int B)
{
    __shared__ float2 pW2[HID * 32];   // pW2[k*32+l] = {W2[l][k], W2[l+32][k]}
    __shared__ float2 pW3[HID * 32];
    __shared__ float2 sAct[8][HID];    // per-warp masked-activation pairs

    const int tid = threadIdx.x;
    for (int idx = tid; idx < HID * HID; idx += 256) {
        int o = idx >> 6, k = idx & 63;
        float w2 = W2[idx], w3 = W3[idx];
        if (o < 32) { pW2[k * 32 + o].x = w2; pW3[k * 32 + o].x = w3; }
        else        { pW2[k * 32 + o - 32].y = w2; pW3[k * 32 + o - 32].y = w3; }
    }
    __syncthreads();

    const int w = tid >> 5;
    const int l = tid & 31;
    const int smp = blockIdx.x * 8 + w;
    if (smp >= B) return;

    const int o0 = l, o1 = l + 32;

    const float xi  = x[smp];
    const float c0i = g_c0[smp];

    const float a1lo = __fmaf_rn(W1[o0 * 3 + 0], xi, __fmaf_rn(W1[o0 * 3 + 2], c0i, b1[o0]));
    const float a1hi = __fmaf_rn(W1[o1 * 3 + 0], xi, __fmaf_rn(W1[o1 * 3 + 2], c0i, b1[o1]));
    const float wylo = W1[o0 * 3 + 1];
    const float wyhi = W1[o1 * 3 + 1];
    const float b2lo = b2[o0], b2hi = b2[o1];
    const float b3lo = b3[o0], b3hi = b3[o1];
    const float w4lo = W4[o0], w4hi = W4[o1];

    float2* act = sAct[w];

    float y = 0.0f;                       // Y_MEAN
    float t0 = 0.f, t1 = 0.f, ub0 = 0.f, ub1 = 0.f;
    float s0 = 0.f, s1 = 0.f, rb0 = 0.f, rb1 = 0.f;
    float gy = 0.0f;
    unsigned prevpk = 0u;
    bool force = true;

    for (int step = 0; step < STEPS; ++step) {
        // speculative affine evaluation (exact whenever masks unchanged)
        float z1lo = __fmaf_rn(y, wylo, a1lo);
        float z1hi = __fmaf_rn(y, wyhi, a1hi);
        float z2lo = __fmaf_rn(y, t0, ub0);
        float z2hi = __fmaf_rn(y, t1, ub1);
        float z3lo = __fmaf_rn(y, s0, rb0);
        float z3hi = __fmaf_rn(y, s1, rb1);

        unsigned pk = (unsigned)(z1lo > 0.0f)
                    | ((unsigned)(z1hi > 0.0f) << 1)
                    | ((unsigned)(z2lo > 0.0f) << 2)
                    | ((unsigned)(z2hi > 0.0f) << 3)
                    | ((unsigned)(z3lo > 0.0f) << 4)
                    | ((unsigned)(z3hi > 0.0f) << 5);

        unsigned any = __ballot_sync(0xffffffffu, force | (pk != prevpk));
        if (any) {
            // ----- level 1 -----
            bool ch1 = force | ((pk & 3u) != (prevpk & 3u));
            unsigned did1 = __ballot_sync(0xffffffffu, ch1);
            if (did1) {
                bool p0 = z1lo > 0.0f, p1 = z1hi > 0.0f;
                act[o0] = make_float2(p0 ? a1lo : 0.0f, p0 ? wylo : 0.0f);
                act[o1] = make_float2(p1 ? a1hi : 0.0f, p1 ? wyhi : 0.0f);
                __syncwarp();
                float u0 = 0.f, u1 = 0.f;
                t0 = t1 = 0.f;
                #pragma unroll 16
                for (int k = 0; k < HID; ++k) {
                    float2 a  = act[k];
                    float2 wv = pW2[k * 32 + l];
                    u0 = __fmaf_rn(wv.x, a.x, u0);
                    u1 = __fmaf_rn(wv.y, a.x, u1);
                    t0 = __fmaf_rn(wv.x, a.y, t0);
                    t1 = __fmaf_rn(wv.y, a.y, t1);
                }
                __syncwarp();
                ub0 = u0 + b2lo;
                ub1 = u1 + b2hi;
                z2lo = __fmaf_rn(y, t0, ub0);
                z2hi = __fmaf_rn(y, t1, ub1);
            }

            // ----- level 2 (must rerun if level-1 matvec re-ran: ub,t changed) ---
            bool q0 = z2lo > 0.0f, q1 = z2hi > 0.0f;
            unsigned m2now = (unsigned)q0 | ((unsigned)q1 << 1);
            bool ch2 = m2now != ((prevpk >> 2) & 3u);
            unsigned did2 = did1 | __ballot_sync(0xffffffffu, ch2);
            if (did2) {
                act[o0] = make_float2(q0 ? ub0 : 0.0f, q0 ? t0 : 0.0f);
                act[o1] = make_float2(q1 ? ub1 : 0.0f, q1 ? t1 : 0.0f);
                __syncwarp();
                float r0 = 0.f, r1 = 0.f;
                s0 = s1 = 0.f;
                #pragma unroll 16
                for (int k = 0; k < HID; ++k) {
                    float2 a  = act[k];
                    float2 wv = pW3[k * 32 + l];
                    r0 = __fmaf_rn(wv.x, a.x, r0);
                    r1 = __fmaf_rn(wv.y, a.x, r1);
                    s0 = __fmaf_rn(wv.x, a.y, s0);
                    s1 = __fmaf_rn(wv.y, a.y, s1);
                }
                __syncwarp();
                rb0 = r0 + b3lo;
                rb1 = r1 + b3hi;
                z3lo = __fmaf_rn(y, s0, rb0);
                z3hi = __fmaf_rn(y, s1, rb1);
            }

            // ----- level 3 + gy (uses fresh s; cheap, redo on every slow entry) --
            bool g0 = z3lo > 0.0f, g1 = z3hi > 0.0f;
            float p = (g0 ? __fmul_rn(w4lo, s0) : 0.0f)
                    + (g1 ? __fmul_rn(w4hi, s1) : 0.0f);
            #pragma unroll
            for (int off = 16; off; off >>= 1)
                p += __shfl_xor_sync(0xffffffffu, p, off);
            gy = p;

            prevpk = (unsigned)(z1lo > 0.0f)
                   | ((unsigned)(z1hi > 0.0f) << 1)
                   | ((unsigned)q0 << 2) | ((unsigned)q1 << 3)
                   | ((unsigned)g0 << 4) | ((unsigned)g1 << 5);
            force = false;
        }

        // y <- y - 0.1*gy (non-fused to mirror JAX rounding)
        y = __fadd_rn(y, -__fmul_rn(0.1f, gy));
    }

    if (l == 0) out[smp] = y;
}

// ---------------------------------------------------------------------------
// Inputs (metadata order):
//   0:x [B] 1:c [B] 2:W1 [64*3] 3:b1 [64] 4:W2 [64*64] 5:b2 [64]
//   6:W3 [64*64] 7:b3 [64] 8:W4 [64] 9:b4 [1] (unused: gy independent of b4)
// ---------------------------------------------------------------------------
extern "C" void kernel_launch(void* const* d_in, const int* in_sizes, int n_in,
                              void* d_out, int out_size)
{
    const float* x  = (const float*)d_in[0];
    const float* c  = (const float*)d_in[1];
    const float* W1 = (const float*)d_in[2];
    const float* b1 = (const float*)d_in[3];
    const float* W2 = (const float*)d_in[4];
    const float* b2 = (const float*)d_in[5];
    const float* W3 = (const float*)d_in[6];
    const float* b3 = (const float*)d_in[7];
    const float* W4 = (const float*)d_in[8];
    float* out = (float*)d_out;

    const int B = in_sizes[0];   // 8192

    // 1) nearest neighbor -> g_c0   (8 lanes per sample, full chip)
    nn_kernel<<<(B * 8) / 256, 256>>>(c, B);

    // 2) warp-per-sample solve: 8 samples per 256-thread block
    solve_kernel<<<(B + 7) / 8, 256>>>(x, W1, b1, W2, b2, W3, b3, W4, out, B);
}

// round 5
// speedup vs baseline: 1.2345x; 1.2345x over previous
#include <cuda_runtime.h>
#include <cuda_bf16.h>

#define NB      8192
#define STEPS   50
#define HID     64

// ---------------------------------------------------------------------------
// One fused kernel: per-warp 1-D nearest neighbor + 50-step solve with
// piecewise-linear affine caching and RANK-1 incremental mask updates.
//
// E is piecewise-linear in y (ReLU MLP, linear head) -> gy piecewise-constant.
// Cached affine forms (valid while masks constant):
//   z1 = a1 + y*w1y ; z2 = ub + y*t ; z3 = rb + y*s ; gy = sum m3.*W4.*s
// Steady step = 6 FMA + 1 ballot. On a mask-change event:
//   m1 bit k flips  -> (ub,t)  ±= (a1[k],w1y[k]) * W2[:,k]    (rank-1)
//                      then one full W3 matvec (inputs changed densely)
//   m2 bit j flips  -> (rb,s)  ±= (ub[j],t[j]) * W3[:,j]      (rank-1)
//   m3 flips        -> gy re-reduced (cheap)
// Full matvec fallback on force / >6 flips (also resets fp drift).
// ---------------------------------------------------------------------------
__global__ void __launch_bounds__(256) solve_kernel(
    const float* __restrict__ x,  const float* __restrict__ c,
    const float* __restrict__ W1, const float* __restrict__ b1,
    const float* __restrict__ W2, const float* __restrict__ b2,
    const float* __restrict__ W3, const float* __restrict__ b3,
    const float* __restrict__ W4,
    float* __restrict__ out, int B)
{
    __shared__ float2 pW2[HID * 32];   // pW2[k*32+l] = {W2[l][k], W2[l+32][k]}
    __shared__ float2 pW3[HID * 32];   // pW3[j*32+l] = {W3[l][j], W3[l+32][j]}
    __shared__ float2 sAct[8][HID];    // per-warp masked-activation pairs

    const int tid = threadIdx.x;
    for (int idx = tid; idx < HID * HID; idx += 256) {
        int o = idx >> 6, k = idx & 63;
        float w2 = W2[idx], w3 = W3[idx];
        if (o < 32) { pW2[k * 32 + o].x = w2; pW3[k * 32 + o].x = w3; }
        else        { pW2[k * 32 + o - 32].y = w2; pW3[k * 32 + o - 32].y = w3; }
    }
    __syncthreads();

    const int w = tid >> 5;
    const int l = tid & 31;
    const int smp = blockIdx.x * 8 + w;
    if (smp >= B) return;

    // ---- nearest neighbor (CD=1: metric == |ci-cj|), lanes scan 256-chunks --
    const float ci = c[smp];
    float best = 3.0e38f;
    int   bj   = l * 256;
    {
        const float4* c4 = (const float4*)(c + l * 256);
        #pragma unroll 4
        for (int q = 0; q < NB / 32 / 4; ++q) {
            float4 v = c4[q];
            int j = l * 256 + q * 4;
            float d0 = fabsf(ci - v.x); d0 = (j + 0 == smp) ? 3.0e38f : d0;
            if (d0 < best) { best = d0; bj = j + 0; }
            float d1 = fabsf(ci - v.y); d1 = (j + 1 == smp) ? 3.0e38f : d1;
            if (d1 < best) { best = d1; bj = j + 1; }
            float d2 = fabsf(ci - v.z); d2 = (j + 2 == smp) ? 3.0e38f : d2;
            if (d2 < best) { best = d2; bj = j + 2; }
            float d3 = fabsf(ci - v.w); d3 = (j + 3 == smp) ? 3.0e38f : d3;
            if (d3 < best) { best = d3; bj = j + 3; }
        }
        // lexicographic (dist, index) merge preserves argmin-first-index
        #pragma unroll
        for (int off = 16; off; off >>= 1) {
            float ob = __shfl_xor_sync(0xffffffffu, best, off);
            int   oj = __shfl_xor_sync(0xffffffffu, bj,   off);
            if (ob < best || (ob == best && oj < bj)) { best = ob; bj = oj; }
        }
    }
    const float c0i = c[bj];

    // ---- per-lane constants ----
    const int o0 = l, o1 = l + 32;
    const float xi = x[smp];
    const float a1lo = __fmaf_rn(W1[o0 * 3 + 0], xi, __fmaf_rn(W1[o0 * 3 + 2], c0i, b1[o0]));
    const float a1hi = __fmaf_rn(W1[o1 * 3 + 0], xi, __fmaf_rn(W1[o1 * 3 + 2], c0i, b1[o1]));
    const float wylo = W1[o0 * 3 + 1];
    const float wyhi = W1[o1 * 3 + 1];
    const float b2lo = b2[o0], b2hi = b2[o1];
    const float b3lo = b3[o0], b3hi = b3[o1];
    const float w4lo = W4[o0], w4hi = W4[o1];

    float2* act = sAct[w];

    float y = 0.0f;                       // Y_MEAN
    float t0 = 0.f, t1 = 0.f, ub0 = 0.f, ub1 = 0.f;   // ub includes +b2
    float s0 = 0.f, s1 = 0.f, rb0 = 0.f, rb1 = 0.f;   // rb includes +b3
    float gy = 0.0f;
    unsigned prevpk = 0u;
    bool force = true;

    for (int step = 0; step < STEPS; ++step) {
        // speculative affine evaluation (exact while masks unchanged)
        float z1lo = __fmaf_rn(y, wylo, a1lo);
        float z1hi = __fmaf_rn(y, wyhi, a1hi);
        float z2lo = __fmaf_rn(y, t0, ub0);
        float z2hi = __fmaf_rn(y, t1, ub1);
        float z3lo = __fmaf_rn(y, s0, rb0);
        float z3hi = __fmaf_rn(y, s1, rb1);

        unsigned pk = (unsigned)(z1lo > 0.0f)
                    | ((unsigned)(z1hi > 0.0f) << 1)
                    | ((unsigned)(z2lo > 0.0f) << 2)
                    | ((unsigned)(z2hi > 0.0f) << 3)
                    | ((unsigned)(z3lo > 0.0f) << 4)
                    | ((unsigned)(z3hi > 0.0f) << 5);

        unsigned any = __ballot_sync(0xffffffffu, force | (pk != prevpk));
        if (any) {
            const unsigned d = pk ^ prevpk;

            // ---------- level 1 ----------
            unsigned f1a = __ballot_sync(0xffffffffu, (d & 1u) != 0u);
            unsigned f1b = __ballot_sync(0xffffffffu, (d & 2u) != 0u);
            int n1 = __popc(f1a) + __popc(f1b);
            bool full1 = force || (n1 > 6);
            if (full1) {
                bool p0 = z1lo > 0.0f, p1 = z1hi > 0.0f;
                act[o0] = make_float2(p0 ? a1lo : 0.0f, p0 ? wylo : 0.0f);
                act[o1] = make_float2(p1 ? a1hi : 0.0f, p1 ? wyhi : 0.0f);
                __syncwarp();
                float u0 = 0.f, u1 = 0.f;
                t0 = t1 = 0.f;
                #pragma unroll 16
                for (int k = 0; k < HID; ++k) {
                    float2 a  = act[k];
                    float2 wv = pW2[k * 32 + l];
                    u0 = __fmaf_rn(wv.x, a.x, u0);
                    u1 = __fmaf_rn(wv.y, a.x, u1);
                    t0 = __fmaf_rn(wv.x, a.y, t0);
                    t1 = __fmaf_rn(wv.y, a.y, t1);
                }
                __syncwarp();
                ub0 = u0 + b2lo;
                ub1 = u1 + b2hi;
            } else if (n1) {
                // rank-1 AXPY per flipped m1 bit (sign = NEW state)
                float sa_lo = (z1lo > 0.0f) ? a1lo : -a1lo;
                float st_lo = (z1lo > 0.0f) ? wylo : -wylo;
                float sa_hi = (z1hi > 0.0f) ? a1hi : -a1hi;
                float st_hi = (z1hi > 0.0f) ? wyhi : -wyhi;
                for (unsigned m = f1a; m; m &= m - 1u) {
                    int k = __ffs(m) - 1;
                    float ca = __shfl_sync(0xffffffffu, sa_lo, k);
                    float ct = __shfl_sync(0xffffffffu, st_lo, k);
                    float2 wv = pW2[k * 32 + l];
                    ub0 = __fmaf_rn(ca, wv.x, ub0); ub1 = __fmaf_rn(ca, wv.y, ub1);
                    t0  = __fmaf_rn(ct, wv.x, t0);  t1  = __fmaf_rn(ct, wv.y, t1);
                }
                for (unsigned m = f1b; m; m &= m - 1u) {
                    int k = __ffs(m) - 1;
                    float ca = __shfl_sync(0xffffffffu, sa_hi, k);
                    float ct = __shfl_sync(0xffffffffu, st_hi, k);
                    float2 wv = pW2[(k + 32) * 32 + l];
                    ub0 = __fmaf_rn(ca, wv.x, ub0); ub1 = __fmaf_rn(ca, wv.y, ub1);
                    t0  = __fmaf_rn(ct, wv.x, t0);  t1  = __fmaf_rn(ct, wv.y, t1);
                }
            }
            const bool l1ran = full1 || (n1 > 0);
            if (l1ran) {
                z2lo = __fmaf_rn(y, t0, ub0);
                z2hi = __fmaf_rn(y, t1, ub1);
            }

            // ---------- level 2 ----------
            bool q0 = z2lo > 0.0f, q1 = z2hi > 0.0f;
            if (l1ran) {
                // (ub,t) changed densely -> full W3 matvec with m2_new
                act[o0] = make_float2(q0 ? ub0 : 0.0f, q0 ? t0 : 0.0f);
                act[o1] = make_float2(q1 ? ub1 : 0.0f, q1 ? t1 : 0.0f);
                __syncwarp();
                float r0 = 0.f, r1 = 0.f;
                s0 = s1 = 0.f;
                #pragma unroll 16
                for (int k = 0; k < HID; ++k) {
                    float2 a  = act[k];
                    float2 wv = pW3[k * 32 + l];
                    r0 = __fmaf_rn(wv.x, a.x, r0);
                    r1 = __fmaf_rn(wv.y, a.x, r1);
                    s0 = __fmaf_rn(wv.x, a.y, s0);
                    s1 = __fmaf_rn(wv.y, a.y, s1);
                }
                __syncwarp();
                rb0 = r0 + b3lo;
                rb1 = r1 + b3hi;
                z3lo = __fmaf_rn(y, s0, rb0);
                z3hi = __fmaf_rn(y, s1, rb1);
            } else {
                unsigned f2a = __ballot_sync(0xffffffffu, q0 != (bool)((prevpk >> 2) & 1u));
                unsigned f2b = __ballot_sync(0xffffffffu, q1 != (bool)((prevpk >> 3) & 1u));
                if (f2a | f2b) {
                    // rank-1 per flipped m2 bit: (rb,s) ±= (ub[j], t[j]) * W3[:,j]
                    float su_lo = q0 ? ub0 : -ub0;
                    float sv_lo = q0 ? t0  : -t0;
                    float su_hi = q1 ? ub1 : -ub1;
                    float sv_hi = q1 ? t1  : -t1;
                    for (unsigned m = f2a; m; m &= m - 1u) {
                        int j = __ffs(m) - 1;
                        float cu = __shfl_sync(0xffffffffu, su_lo, j);
                        float cv = __shfl_sync(0xffffffffu, sv_lo, j);
                        float2 wv = pW3[j * 32 + l];
                        rb0 = __fmaf_rn(cu, wv.x, rb0); rb1 = __fmaf_rn(cu, wv.y, rb1);
                        s0  = __fmaf_rn(cv, wv.x, s0);  s1  = __fmaf_rn(cv, wv.y, s1);
                    }
                    for (unsigned m = f2b; m; m &= m - 1u) {
                        int j = __ffs(m) - 1;
                        float cu = __shfl_sync(0xffffffffu, su_hi, j);
                        float cv = __shfl_sync(0xffffffffu, sv_hi, j);
                        float2 wv = pW3[(j + 32) * 32 + l];
                        rb0 = __fmaf_rn(cu, wv.x, rb0); rb1 = __fmaf_rn(cu, wv.y, rb1);
                        s0  = __fmaf_rn(cv, wv.x, s0);  s1  = __fmaf_rn(cv, wv.y, s1);
                    }
                    z3lo = __fmaf_rn(y, s0, rb0);
                    z3hi = __fmaf_rn(y, s1, rb1);
                }
            }

            // ---------- level 3 + gy (cheap, every slow entry) ----------
            bool g0 = z3lo > 0.0f, g1 = z3hi > 0.0f;
            float p = (g0 ? __fmul_rn(w4lo, s0) : 0.0f)
                    + (g1 ? __fmul_rn(w4hi, s1) : 0.0f);
            #pragma unroll
            for (int off = 16; off; off >>= 1)
                p += __shfl_xor_sync(0xffffffffu, p, off);
            gy = p;

            prevpk = (unsigned)(z1lo > 0.0f)
                   | ((unsigned)(z1hi > 0.0f) << 1)
                   | ((unsigned)q0 << 2) | ((unsigned)q1 << 3)
                   | ((unsigned)g0 << 4) | ((unsigned)g1 << 5);
            force = false;
        }

        // y <- y - 0.1*gy (non-fused to mirror JAX rounding)
        y = __fadd_rn(y, -__fmul_rn(0.1f, gy));
    }

    if (l == 0) out[smp] = y;
}

// ---------------------------------------------------------------------------
// Inputs (metadata order):
//   0:x [B] 1:c [B] 2:W1 [64*3] 3:b1 [64] 4:W2 [64*64] 5:b2 [64]
//   6:W3 [64*64] 7:b3 [64] 8:W4 [64] 9:b4 [1] (unused: gy independent of b4)
// ---------------------------------------------------------------------------
extern "C" void kernel_launch(void* const* d_in, const int* in_sizes, int n_in,
                              void* d_out, int out_size)
{
    const float* x  = (const float*)d_in[0];
    const float* c  = (const float*)d_in[1];
    const float* W1 = (const float*)d_in[2];
    const float* b1 = (const float*)d_in[3];
    const float* W2 = (const float*)d_in[4];
    const float* b2 = (const float*)d_in[5];
    const float* W3 = (const float*)d_in[6];
    const float* b3 = (const float*)d_in[7];
    const float* W4 = (const float*)d_in[8];
    float* out = (float*)d_out;

    const int B = in_sizes[0];   // 8192

    // single fused kernel: NN + solve, 8 samples (warps) per block
    solve_kernel<<<(B + 7) / 8, 256>>>(x, c, W1, b1, W2, b2, W3, b3, W4, out, B);
}

// round 7
// speedup vs baseline: 1.7529x; 1.4199x over previous
#include <cuda_runtime.h>
#include <cuda_bf16.h>

#define NB      8192
#define STEPS   50
#define HID     64

// ---------------------------------------------------------------------------
// One fused kernel: per-warp 1-D nearest neighbor + 50-step solve with
// piecewise-linear affine caching and RANK-1 incremental mask updates.
//
// E is piecewise-linear in y (ReLU MLP, linear head) -> gy piecewise-constant.
// Cached affine forms (valid while masks constant):
//   z1 = a1 + y*w1y ; z2 = ub + y*t ; z3 = rb + y*s ; gy = sum m3.*W4.*s
// Steady step = 6 FMA + 1 ballot. On a mask-change event:
//   m1 bit k flips  -> (ub,t)  ±= (a1[k],w1y[k]) * W2[:,k]    (rank-1)
//                      then one full W3 matvec (inputs changed densely)
//   m2 bit j flips  -> (rb,s)  ±= (ub[j],t[j]) * W3[:,j]      (rank-1)
//   m3 flips        -> gy re-reduced (cheap)
// Full matvec fallback on force / >6 flips (also resets fp drift).
//
// R6 change: NN scan is INTERLEAVED (lane l reads c4[q*32+l]) -> coalesced
// 512B warp-loads (4 L1 wavefronts instead of 32). Per-lane index order is
// still increasing, so strict-< + lexicographic merge preserves the exact
// argmin-first-index semantics of the reference.
// ---------------------------------------------------------------------------
__global__ void __launch_bounds__(256) solve_kernel(
    const float* __restrict__ x,  const float* __restrict__ c,
    const float* __restrict__ W1, const float* __restrict__ b1,
    const float* __restrict__ W2, const float* __restrict__ b2,
    const float* __restrict__ W3, const float* __restrict__ b3,
    const float* __restrict__ W4,
    float* __restrict__ out, int B)
{
    __shared__ float2 pW2[HID * 32];   // pW2[k*32+l] = {W2[l][k], W2[l+32][k]}
    __shared__ float2 pW3[HID * 32];   // pW3[j*32+l] = {W3[l][j], W3[l+32][j]}
    __shared__ float2 sAct[8][HID];    // per-warp masked-activation pairs

    const int tid = threadIdx.x;
    for (int idx = tid; idx < HID * HID; idx += 256) {
        int o = idx >> 6, k = idx & 63;
        float w2 = W2[idx], w3 = W3[idx];
        if (o < 32) { pW2[k * 32 + o].x = w2; pW3[k * 32 + o].x = w3; }
        else        { pW2[k * 32 + o - 32].y = w2; pW3[k * 32 + o - 32].y = w3; }
    }
    __syncthreads();

    const int w = tid >> 5;
    const int l = tid & 31;
    const int smp = blockIdx.x * 8 + w;
    if (smp >= B) return;

    // ---- nearest neighbor (CD=1: metric == |ci-cj|), coalesced interleave --
    const float ci = c[smp];
    float best = 3.0e38f;
    int   bj   = l * 4;
    {
        const float4* c4 = (const float4*)c;
        #pragma unroll 4
        for (int q = 0; q < NB / 128; ++q) {          // 64 iterations
            float4 v = c4[q * 32 + l];                // contiguous per warp
            int j = q * 128 + l * 4;
            float d0 = fabsf(ci - v.x); d0 = (j + 0 == smp) ? 3.0e38f : d0;
            if (d0 < best) { best = d0; bj = j + 0; }
            float d1 = fabsf(ci - v.y); d1 = (j + 1 == smp) ? 3.0e38f : d1;
            if (d1 < best) { best = d1; bj = j + 1; }
            float d2 = fabsf(ci - v.z); d2 = (j + 2 == smp) ? 3.0e38f : d2;
            if (d2 < best) { best = d2; bj = j + 2; }
            float d3 = fabsf(ci - v.w); d3 = (j + 3 == smp) ? 3.0e38f : d3;
            if (d3 < best) { best = d3; bj = j + 3; }
        }
        // lexicographic (dist, index) merge preserves argmin-first-index
        #pragma unroll
        for (int off = 16; off; off >>= 1) {
            float ob = __shfl_xor_sync(0xffffffffu, best, off);
            int   oj = __shfl_xor_sync(0xffffffffu, bj,   off);
            if (ob < best || (ob == best && oj < bj)) { best = ob; bj = oj; }
        }
    }
    const float c0i = c[bj];

    // ---- per-lane constants ----
    const int o0 = l, o1 = l + 32;
    const float xi = x[smp];
    const float a1lo = __fmaf_rn(W1[o0 * 3 + 0], xi, __fmaf_rn(W1[o0 * 3 + 2], c0i, b1[o0]));
    const float a1hi = __fmaf_rn(W1[o1 * 3 + 0], xi, __fmaf_rn(W1[o1 * 3 + 2], c0i, b1[o1]));
    const float wylo = W1[o0 * 3 + 1];
    const float wyhi = W1[o1 * 3 + 1];
    const float b2lo = b2[o0], b2hi = b2[o1];
    const float b3lo = b3[o0], b3hi = b3[o1];
    const float w4lo = W4[o0], w4hi = W4[o1];

    float2* act = sAct[w];

    float y = 0.0f;                       // Y_MEAN
    float t0 = 0.f, t1 = 0.f, ub0 = 0.f, ub1 = 0.f;   // ub includes +b2
    float s0 = 0.f, s1 = 0.f, rb0 = 0.f, rb1 = 0.f;   // rb includes +b3
    float gy = 0.0f;
    unsigned prevpk = 0u;
    bool force = true;

    for (int step = 0; step < STEPS; ++step) {
        // speculative affine evaluation (exact while masks unchanged)
        float z1lo = __fmaf_rn(y, wylo, a1lo);
        float z1hi = __fmaf_rn(y, wyhi, a1hi);
        float z2lo = __fmaf_rn(y, t0, ub0);
        float z2hi = __fmaf_rn(y, t1, ub1);
        float z3lo = __fmaf_rn(y, s0, rb0);
        float z3hi = __fmaf_rn(y, s1, rb1);

        unsigned pk = (unsigned)(z1lo > 0.0f)
                    | ((unsigned)(z1hi > 0.0f) << 1)
                    | ((unsigned)(z2lo > 0.0f) << 2)
                    | ((unsigned)(z2hi > 0.0f) << 3)
                    | ((unsigned)(z3lo > 0.0f) << 4)
                    | ((unsigned)(z3hi > 0.0f) << 5);

        unsigned any = __ballot_sync(0xffffffffu, force | (pk != prevpk));
        if (any) {
            const unsigned d = pk ^ prevpk;

            // ---------- level 1 ----------
            unsigned f1a = __ballot_sync(0xffffffffu, (d & 1u) != 0u);
            unsigned f1b = __ballot_sync(0xffffffffu, (d & 2u) != 0u);
            int n1 = __popc(f1a) + __popc(f1b);
            bool full1 = force || (n1 > 6);
            if (full1) {
                bool p0 = z1lo > 0.0f, p1 = z1hi > 0.0f;
                act[o0] = make_float2(p0 ? a1lo : 0.0f, p0 ? wylo : 0.0f);
                act[o1] = make_float2(p1 ? a1hi : 0.0f, p1 ? wyhi : 0.0f);
                __syncwarp();
                float u0 = 0.f, u1 = 0.f;
                t0 = t1 = 0.f;
                #pragma unroll 16
                for (int k = 0; k < HID; ++k) {
                    float2 a  = act[k];
                    float2 wv = pW2[k * 32 + l];
                    u0 = __fmaf_rn(wv.x, a.x, u0);
                    u1 = __fmaf_rn(wv.y, a.x, u1);
                    t0 = __fmaf_rn(wv.x, a.y, t0);
                    t1 = __fmaf_rn(wv.y, a.y, t1);
                }
                __syncwarp();
                ub0 = u0 + b2lo;
                ub1 = u1 + b2hi;
            } else if (n1) {
                // rank-1 AXPY per flipped m1 bit (sign = NEW state)
                float sa_lo = (z1lo > 0.0f) ? a1lo : -a1lo;
                float st_lo = (z1lo > 0.0f) ? wylo : -wylo;
                float sa_hi = (z1hi > 0.0f) ? a1hi : -a1hi;
                float st_hi = (z1hi > 0.0f) ? wyhi : -wyhi;
                for (unsigned m = f1a; m; m &= m - 1u) {
                    int k = __ffs(m) - 1;
                    float ca = __shfl_sync(0xffffffffu, sa_lo, k);
                    float ct = __shfl_sync(0xffffffffu, st_lo, k);
                    float2 wv = pW2[k * 32 + l];
                    ub0 = __fmaf_rn(ca, wv.x, ub0); ub1 = __fmaf_rn(ca, wv.y, ub1);
                    t0  = __fmaf_rn(ct, wv.x, t0);  t1  = __fmaf_rn(ct, wv.y, t1);
                }
                for (unsigned m = f1b; m; m &= m - 1u) {
                    int k = __ffs(m) - 1;
                    float ca = __shfl_sync(0xffffffffu, sa_hi, k);
                    float ct = __shfl_sync(0xffffffffu, st_hi, k);
                    float2 wv = pW2[(k + 32) * 32 + l];
                    ub0 = __fmaf_rn(ca, wv.x, ub0); ub1 = __fmaf_rn(ca, wv.y, ub1);
                    t0  = __fmaf_rn(ct, wv.x, t0);  t1  = __fmaf_rn(ct, wv.y, t1);
                }
            }
            const bool l1ran = full1 || (n1 > 0);
            if (l1ran) {
                z2lo = __fmaf_rn(y, t0, ub0);
                z2hi = __fmaf_rn(y, t1, ub1);
            }

            // ---------- level 2 ----------
            bool q0 = z2lo > 0.0f, q1 = z2hi > 0.0f;
            if (l1ran) {
                // (ub,t) changed densely -> full W3 matvec with m2_new
                act[o0] = make_float2(q0 ? ub0 : 0.0f, q0 ? t0 : 0.0f);
                act[o1] = make_float2(q1 ? ub1 : 0.0f, q1 ? t1 : 0.0f);
                __syncwarp();
                float r0 = 0.f, r1 = 0.f;
                s0 = s1 = 0.f;
                #pragma unroll 16
                for (int k = 0; k < HID; ++k) {
                    float2 a  = act[k];
                    float2 wv = pW3[k * 32 + l];
                    r0 = __fmaf_rn(wv.x, a.x, r0);
                    r1 = __fmaf_rn(wv.y, a.x, r1);
                    s0 = __fmaf_rn(wv.x, a.y, s0);
                    s1 = __fmaf_rn(wv.y, a.y, s1);
                }
                __syncwarp();
                rb0 = r0 + b3lo;
                rb1 = r1 + b3hi;
                z3lo = __fmaf_rn(y, s0, rb0);
                z3hi = __fmaf_rn(y, s1, rb1);
            } else {
                unsigned f2a = __ballot_sync(0xffffffffu, q0 != (bool)((prevpk >> 2) & 1u));
                unsigned f2b = __ballot_sync(0xffffffffu, q1 != (bool)((prevpk >> 3) & 1u));
                if (f2a | f2b) {
                    // rank-1 per flipped m2 bit: (rb,s) ±= (ub[j], t[j]) * W3[:,j]
                    float su_lo = q0 ? ub0 : -ub0;
                    float sv_lo = q0 ? t0  : -t0;
                    float su_hi = q1 ? ub1 : -ub1;
                    float sv_hi = q1 ? t1  : -t1;
                    for (unsigned m = f2a; m; m &= m - 1u) {
                        int j = __ffs(m) - 1;
                        float cu = __shfl_sync(0xffffffffu, su_lo, j);
                        float cv = __shfl_sync(0xffffffffu, sv_lo, j);
                        float2 wv = pW3[j * 32 + l];
                        rb0 = __fmaf_rn(cu, wv.x, rb0); rb1 = __fmaf_rn(cu, wv.y, rb1);
                        s0  = __fmaf_rn(cv, wv.x, s0);  s1  = __fmaf_rn(cv, wv.y, s1);
                    }
                    for (unsigned m = f2b; m; m &= m - 1u) {
                        int j = __ffs(m) - 1;
                        float cu = __shfl_sync(0xffffffffu, su_hi, j);
                        float cv = __shfl_sync(0xffffffffu, sv_hi, j);
                        float2 wv = pW3[(j + 32) * 32 + l];
                        rb0 = __fmaf_rn(cu, wv.x, rb0); rb1 = __fmaf_rn(cu, wv.y, rb1);
                        s0  = __fmaf_rn(cv, wv.x, s0);  s1  = __fmaf_rn(cv, wv.y, s1);
                    }
                    z3lo = __fmaf_rn(y, s0, rb0);
                    z3hi = __fmaf_rn(y, s1, rb1);
                }
            }

            // ---------- level 3 + gy (cheap, every slow entry) ----------
            bool g0 = z3lo > 0.0f, g1 = z3hi > 0.0f;
            float p = (g0 ? __fmul_rn(w4lo, s0) : 0.0f)
                    + (g1 ? __fmul_rn(w4hi, s1) : 0.0f);
            #pragma unroll
            for (int off = 16; off; off >>= 1)
                p += __shfl_xor_sync(0xffffffffu, p, off);
            gy = p;

            prevpk = (unsigned)(z1lo > 0.0f)
                   | ((unsigned)(z1hi > 0.0f) << 1)
                   | ((unsigned)q0 << 2) | ((unsigned)q1 << 3)
                   | ((unsigned)g0 << 4) | ((unsigned)g1 << 5);
            force = false;
        }

        // y <- y - 0.1*gy (non-fused to mirror JAX rounding)
        y = __fadd_rn(y, -__fmul_rn(0.1f, gy));
    }

    if (l == 0) out[smp] = y;
}

// ---------------------------------------------------------------------------
// Inputs (metadata order):
//   0:x [B] 1:c [B] 2:W1 [64*3] 3:b1 [64] 4:W2 [64*64] 5:b2 [64]
//   6:W3 [64*64] 7:b3 [64] 8:W4 [64] 9:b4 [1] (unused: gy independent of b4)
// ---------------------------------------------------------------------------
extern "C" void kernel_launch(void* const* d_in, const int* in_sizes, int n_in,
                              void* d_out, int out_size)
{
    const float* x  = (const float*)d_in[0];
    const float* c  = (const float*)d_in[1];
    const float* W1 = (const float*)d_in[2];
    const float* b1 = (const float*)d_in[3];
    const float* W2 = (const float*)d_in[4];
    const float* b2 = (const float*)d_in[5];
    const float* W3 = (const float*)d_in[6];
    const float* b3 = (const float*)d_in[7];
    const float* W4 = (const float*)d_in[8];
    float* out = (float*)d_out;

    const int B = in_sizes[0];   // 8192

    // single fused kernel: NN + solve, 8 samples (warps) per block
    solve_kernel<<<(B + 7) / 8, 256>>>(x, c, W1, b1, W2, b2, W3, b3, W4, out, B);
}

// round 8
// speedup vs baseline: 1.9813x; 1.1303x over previous
#include <cuda_runtime.h>
#include <cuda_bf16.h>

#define NB      8192
#define STEPS   50
#define HID     64

// ---------------------------------------------------------------------------
// One fused kernel: NN (smem-staged) + 50-step solve with piecewise-linear
// affine caching and rank-1 incremental mask updates.
//
// Phase-ordered shared memory reuse: buf holds c[8192] during the NN scan,
// then is overwritten with the float4-packed W2/W3 (32 KB either way), so
// smem stays ~37 KB and occupancy is unchanged.
//
// Matvecs: pW[q*32+l] = {W[l][2q], W[l+32][2q], W[l][2q+1], W[l+32][2q+1]}
// -> one LDS.128 per 2 k-columns; accumulation order k=0..63 preserved
// (bit-identical to the float2 version).
// ---------------------------------------------------------------------------
__global__ void __launch_bounds__(256) solve_kernel(
    const float* __restrict__ x,  const float* __restrict__ c,
    const float* __restrict__ W1, const float* __restrict__ b1,
    const float* __restrict__ W2, const float* __restrict__ b2,
    const float* __restrict__ W3, const float* __restrict__ b3,
    const float* __restrict__ W4,
    float* __restrict__ out, int B)
{
    __shared__ __align__(16) char buf[32768];   // phase A: c[8192]; phase B: W2f4|W3f4
    __shared__ float4 sAct4[8][HID / 2];        // per-warp activation pairs (float2[64])

    const int tid = threadIdx.x;
    const int w = tid >> 5, l = tid & 31;
    const int smp = min(blockIdx.x * 8 + w, B - 1);

    // ---------------- phase A: stage c, per-warp NN scan ----------------
    float* sc = (float*)buf;
    {
        const float4* c4 = (const float4*)c;
        float4* s4 = (float4*)buf;
        #pragma unroll
        for (int i = 0; i < NB / 4 / 256; ++i) s4[tid + i * 256] = c4[tid + i * 256];
    }
    __syncthreads();

    const float ci = sc[smp];
    float c0i;
    {
        // interleaved float2 scan: lane l reads elements (q*32+l)*2 and +1.
        // Two independent compare chains (even/odd), lexicographic merge ->
        // exact argmin-first-index semantics of the reference.
        const float2* sc2 = (const float2*)buf;
        float bx = 3.0e38f, by = 3.0e38f;
        int   jx = 0,       jy = 1;
        #pragma unroll 4
        for (int q = 0; q < NB / 64; ++q) {
            float2 v = sc2[q * 32 + l];
            int j = (q * 32 + l) * 2;
            float dx = fabsf(ci - v.x); if (j == smp)     dx = 3.0e38f;
            if (dx < bx) { bx = dx; jx = j; }
            float dy = fabsf(ci - v.y); if (j + 1 == smp) dy = 3.0e38f;
            if (dy < by) { by = dy; jy = j + 1; }
        }
        float best = bx; int bj = jx;
        if (by < best || (by == best && jy < bj)) { best = by; bj = jy; }
        #pragma unroll
        for (int off = 16; off; off >>= 1) {
            float ob = __shfl_xor_sync(0xffffffffu, best, off);
            int   oj = __shfl_xor_sync(0xffffffffu, bj,   off);
            if (ob < best || (ob == best && oj < bj)) { best = ob; bj = oj; }
        }
        c0i = sc[bj];
    }
    __syncthreads();   // everyone done reading sc

    // ---------------- phase B: pack weights into float4 layout ----------------
    float4* pW2f4 = (float4*)buf;                // 1024 entries (16 KB)
    float4* pW3f4 = (float4*)(buf + 16384);      // 1024 entries (16 KB)
    for (int idx = tid; idx < HID * HID; idx += 256) {
        int o = idx >> 6, k = idx & 63;
        int slot = (k >> 1) * 32 + (o & 31);
        int comp = (k & 1) * 2 + (o >> 5);       // [lo2q, hi2q, lo2q1, hi2q1]
        ((float*)&pW2f4[slot])[comp] = W2[idx];
        ((float*)&pW3f4[slot])[comp] = W3[idx];
    }
    __syncthreads();

    // ---------------- per-lane constants ----------------
    const int o0 = l, o1 = l + 32;
    const float xi = x[smp];
    const float a1lo = __fmaf_rn(W1[o0 * 3 + 0], xi, __fmaf_rn(W1[o0 * 3 + 2], c0i, b1[o0]));
    const float a1hi = __fmaf_rn(W1[o1 * 3 + 0], xi, __fmaf_rn(W1[o1 * 3 + 2], c0i, b1[o1]));
    const float wylo = W1[o0 * 3 + 1];
    const float wyhi = W1[o1 * 3 + 1];
    const float b2lo = b2[o0], b2hi = b2[o1];
    const float b3lo = b3[o0], b3hi = b3[o1];
    const float w4lo = W4[o0], w4hi = W4[o1];

    float2* act = (float2*)sAct4[w];
    const float4* act4 = (const float4*)sAct4[w];

    float y = 0.0f;                       // Y_MEAN
    float t0 = 0.f, t1 = 0.f, ub0 = 0.f, ub1 = 0.f;   // ub includes +b2
    float s0 = 0.f, s1 = 0.f, rb0 = 0.f, rb1 = 0.f;   // rb includes +b3
    float gy = 0.0f;
    unsigned prevpk = 0u;
    bool force = true;

    for (int step = 0; step < STEPS; ++step) {
        // speculative affine evaluation (exact while masks unchanged)
        float z1lo = __fmaf_rn(y, wylo, a1lo);
        float z1hi = __fmaf_rn(y, wyhi, a1hi);
        float z2lo = __fmaf_rn(y, t0, ub0);
        float z2hi = __fmaf_rn(y, t1, ub1);
        float z3lo = __fmaf_rn(y, s0, rb0);
        float z3hi = __fmaf_rn(y, s1, rb1);

        unsigned pk = (unsigned)(z1lo > 0.0f)
                    | ((unsigned)(z1hi > 0.0f) << 1)
                    | ((unsigned)(z2lo > 0.0f) << 2)
                    | ((unsigned)(z2hi > 0.0f) << 3)
                    | ((unsigned)(z3lo > 0.0f) << 4)
                    | ((unsigned)(z3hi > 0.0f) << 5);

        unsigned any = __ballot_sync(0xffffffffu, force | (pk != prevpk));
        if (any) {
            const unsigned d = pk ^ prevpk;

            // ---------- level 1 ----------
            unsigned f1a = __ballot_sync(0xffffffffu, (d & 1u) != 0u);
            unsigned f1b = __ballot_sync(0xffffffffu, (d & 2u) != 0u);
            int n1 = __popc(f1a) + __popc(f1b);
            bool full1 = force || (n1 > 6);
            if (full1) {
                bool p0 = z1lo > 0.0f, p1 = z1hi > 0.0f;
                act[o0] = make_float2(p0 ? a1lo : 0.0f, p0 ? wylo : 0.0f);
                act[o1] = make_float2(p1 ? a1hi : 0.0f, p1 ? wyhi : 0.0f);
                __syncwarp();
                float u0 = 0.f, u1 = 0.f;
                t0 = t1 = 0.f;
                #pragma unroll 8
                for (int q = 0; q < 32; ++q) {
                    float4 a  = act4[q];               // {b(2q),s(2q),b(2q+1),s(2q+1)}
                    float4 wv = pW2f4[q * 32 + l];
                    u0 = __fmaf_rn(wv.x, a.x, u0); u1 = __fmaf_rn(wv.y, a.x, u1);
                    t0 = __fmaf_rn(wv.x, a.y, t0); t1 = __fmaf_rn(wv.y, a.y, t1);
                    u0 = __fmaf_rn(wv.z, a.z, u0); u1 = __fmaf_rn(wv.w, a.z, u1);
                    t0 = __fmaf_rn(wv.z, a.w, t0); t1 = __fmaf_rn(wv.w, a.w, t1);
                }
                __syncwarp();
                ub0 = u0 + b2lo;
                ub1 = u1 + b2hi;
            } else if (n1) {
                // rank-1 AXPY per flipped m1 bit (sign = NEW state)
                float sa_lo = (z1lo > 0.0f) ? a1lo : -a1lo;
                float st_lo = (z1lo > 0.0f) ? wylo : -wylo;
                float sa_hi = (z1hi > 0.0f) ? a1hi : -a1hi;
                float st_hi = (z1hi > 0.0f) ? wyhi : -wyhi;
                for (unsigned m = f1a; m; m &= m - 1u) {
                    int k = __ffs(m) - 1;
                    float ca = __shfl_sync(0xffffffffu, sa_lo, k);
                    float ct = __shfl_sync(0xffffffffu, st_lo, k);
                    float4 wv = pW2f4[(k >> 1) * 32 + l];
                    float wxc = (k & 1) ? wv.z : wv.x;
                    float wyc = (k & 1) ? wv.w : wv.y;
                    ub0 = __fmaf_rn(ca, wxc, ub0); ub1 = __fmaf_rn(ca, wyc, ub1);
                    t0  = __fmaf_rn(ct, wxc, t0);  t1  = __fmaf_rn(ct, wyc, t1);
                }
                for (unsigned m = f1b; m; m &= m - 1u) {
                    int kk = (__ffs(m) - 1) + 32;
                    float ca = __shfl_sync(0xffffffffu, sa_hi, kk - 32);
                    float ct = __shfl_sync(0xffffffffu, st_hi, kk - 32);
                    float4 wv = pW2f4[(kk >> 1) * 32 + l];
                    float wxc = (kk & 1) ? wv.z : wv.x;
                    float wyc = (kk & 1) ? wv.w : wv.y;
                    ub0 = __fmaf_rn(ca, wxc, ub0); ub1 = __fmaf_rn(ca, wyc, ub1);
                    t0  = __fmaf_rn(ct, wxc, t0);  t1  = __fmaf_rn(ct, wyc, t1);
                }
            }
            const bool l1ran = full1 || (n1 > 0);
            if (l1ran) {
                z2lo = __fmaf_rn(y, t0, ub0);
                z2hi = __fmaf_rn(y, t1, ub1);
            }

            // ---------- level 2 ----------
            bool q0 = z2lo > 0.0f, q1 = z2hi > 0.0f;
            if (l1ran) {
                // (ub,t) changed densely -> full W3 matvec with m2_new
                act[o0] = make_float2(q0 ? ub0 : 0.0f, q0 ? t0 : 0.0f);
                act[o1] = make_float2(q1 ? ub1 : 0.0f, q1 ? t1 : 0.0f);
                __syncwarp();
                float r0 = 0.f, r1 = 0.f;
                s0 = s1 = 0.f;
                #pragma unroll 8
                for (int q = 0; q < 32; ++q) {
                    float4 a  = act4[q];
                    float4 wv = pW3f4[q * 32 + l];
                    r0 = __fmaf_rn(wv.x, a.x, r0); r1 = __fmaf_rn(wv.y, a.x, r1);
                    s0 = __fmaf_rn(wv.x, a.y, s0); s1 = __fmaf_rn(wv.y, a.y, s1);
                    r0 = __fmaf_rn(wv.z, a.z, r0); r1 = __fmaf_rn(wv.w, a.z, r1);
                    s0 = __fmaf_rn(wv.z, a.w, s0); s1 = __fmaf_rn(wv.w, a.w, s1);
                }
                __syncwarp();
                rb0 = r0 + b3lo;
                rb1 = r1 + b3hi;
                z3lo = __fmaf_rn(y, s0, rb0);
                z3hi = __fmaf_rn(y, s1, rb1);
            } else {
                unsigned f2a = __ballot_sync(0xffffffffu, q0 != (bool)((prevpk >> 2) & 1u));
                unsigned f2b = __ballot_sync(0xffffffffu, q1 != (bool)((prevpk >> 3) & 1u));
                if (f2a | f2b) {
                    // rank-1 per flipped m2 bit: (rb,s) ±= (ub[j], t[j]) * W3[:,j]
                    float su_lo = q0 ? ub0 : -ub0;
                    float sv_lo = q0 ? t0  : -t0;
                    float su_hi = q1 ? ub1 : -ub1;
                    float sv_hi = q1 ? t1  : -t1;
                    for (unsigned m = f2a; m; m &= m - 1u) {
                        int j = __ffs(m) - 1;
                        float cu = __shfl_sync(0xffffffffu, su_lo, j);
                        float cv = __shfl_sync(0xffffffffu, sv_lo, j);
                        float4 wv = pW3f4[(j >> 1) * 32 + l];
                        float wxc = (j & 1) ? wv.z : wv.x;
                        float wyc = (j & 1) ? wv.w : wv.y;
                        rb0 = __fmaf_rn(cu, wxc, rb0); rb1 = __fmaf_rn(cu, wyc, rb1);
                        s0  = __fmaf_rn(cv, wxc, s0);  s1  = __fmaf_rn(cv, wyc, s1);
                    }
                    for (unsigned m = f2b; m; m &= m - 1u) {
                        int jj = (__ffs(m) - 1) + 32;
                        float cu = __shfl_sync(0xffffffffu, su_hi, jj - 32);
                        float cv = __shfl_sync(0xffffffffu, sv_hi, jj - 32);
                        float4 wv = pW3f4[(jj >> 1) * 32 + l];
                        float wxc = (jj & 1) ? wv.z : wv.x;
                        float wyc = (jj & 1) ? wv.w : wv.y;
                        rb0 = __fmaf_rn(cu, wxc, rb0); rb1 = __fmaf_rn(cu, wyc, rb1);
                        s0  = __fmaf_rn(cv, wxc, s0);  s1  = __fmaf_rn(cv, wyc, s1);
                    }
                    z3lo = __fmaf_rn(y, s0, rb0);
                    z3hi = __fmaf_rn(y, s1, rb1);
                }
            }

            // ---------- level 3 + gy (cheap, every slow entry) ----------
            bool g0 = z3lo > 0.0f, g1 = z3hi > 0.0f;
            float p = (g0 ? __fmul_rn(w4lo, s0) : 0.0f)
                    + (g1 ? __fmul_rn(w4hi, s1) : 0.0f);
            #pragma unroll
            for (int off = 16; off; off >>= 1)
                p += __shfl_xor_sync(0xffffffffu, p, off);
            gy = p;

            prevpk = (unsigned)(z1lo > 0.0f)
                   | ((unsigned)(z1hi > 0.0f) << 1)
                   | ((unsigned)q0 << 2) | ((unsigned)q1 << 3)
                   | ((unsigned)g0 << 4) | ((unsigned)g1 << 5);
            force = false;
        }

        // y <- y - 0.1*gy (non-fused to mirror JAX rounding)
        y = __fadd_rn(y, -__fmul_rn(0.1f, gy));
    }

    if (l == 0 && blockIdx.x * 8 + w < B) out[smp] = y;
}

// ---------------------------------------------------------------------------
// Inputs (metadata order):
//   0:x [B] 1:c [B] 2:W1 [64*3] 3:b1 [64] 4:W2 [64*64] 5:b2 [64]
//   6:W3 [64*64] 7:b3 [64] 8:W4 [64] 9:b4 [1] (unused: gy independent of b4)
// ---------------------------------------------------------------------------
extern "C" void kernel_launch(void* const* d_in, const int* in_sizes, int n_in,
                              void* d_out, int out_size)
{
    const float* x  = (const float*)d_in[0];
    const float* c  = (const float*)d_in[1];
    const float* W1 = (const float*)d_in[2];
    const float* b1 = (const float*)d_in[3];
    const float* W2 = (const float*)d_in[4];
    const float* b2 = (const float*)d_in[5];
    const float* W3 = (const float*)d_in[6];
    const float* b3 = (const float*)d_in[7];
    const float* W4 = (const float*)d_in[8];
    float* out = (float*)d_out;

    const int B = in_sizes[0];   // 8192

    // single fused kernel: NN + solve, 8 samples (warps) per block
    solve_kernel<<<(B + 7) / 8, 256>>>(x, c, W1, b1, W2, b2, W3, b3, W4, out, B);
}